// round 11
// baseline (speedup 1.0000x reference)
#include <cuda_runtime.h>
#include <cstdint>

// Shapes fixed by reference: d2 [16, 8192, 256] fp32
constexpr int K4 = 64;
constexpr float LAM = 0.95f, OM = 0.05f;
constexpr float L8  = 0.66342043f;   // 0.95^8
constexpr float L16 = 0.44012667f;   // 0.95^16
constexpr float L24 = 0.29198906f;   // 0.95^24
constexpr float L32 = 0.19371148f;   // 0.95^32

constexpr int ST   = 32;                  // timesteps per stage
constexpr int SEG  = 512;                 // main steps per CTA (row-aligned)
constexpr int WS   = 6;                   // warmup stages (192 steps, lam^192 ~ 5e-5)
constexpr int NST  = 3;                   // pipeline depth
constexpr int IST  = ST * K4;             // float4 per stage (2048)
constexpr int STAGE_BYTES = IST * 16;     // 32768
constexpr int SEGR = 8192 / SEG;          // 16 segments per row
constexpr int NCTA = 16 * SEGR;           // 256 CTAs

constexpr int OFF_AGG  = NST * STAGE_BYTES;        // 98304
constexpr int OFF_MBAR = OFF_AGG + 2 * 4 * K4 * 16; // +8192 -> 106496
constexpr int SMEM_BYTES = OFF_MBAR + 64;          // 106560

__device__ __forceinline__ float4 f4fma(float a, float4 u, float4 v) {
    return make_float4(fmaf(a, u.x, v.x), fmaf(a, u.y, v.y),
                       fmaf(a, u.z, v.z), fmaf(a, u.w, v.w));
}
__device__ __forceinline__ float4 f4s(float a, float4 u) {
    return make_float4(a * u.x, a * u.y, a * u.z, a * u.w);
}
__device__ __forceinline__ uint32_t s2u(const void* p) {
    return (uint32_t)__cvta_generic_to_shared(p);
}

__global__ __launch_bounds__(256, 2) void pft_scan(const float4* __restrict__ d2,
                                                   float4* __restrict__ out) {
    extern __shared__ char smem[];
    float4* stg = (float4*)smem;                                   // [NST][IST]
    float4 (*agg)[4][K4] = (float4(*)[4][K4])(smem + OFF_AGG);     // [2][4][64]
    const uint32_t mb0 = s2u(smem + OFF_MBAR);                     // full[0..2]

    const int tid  = threadIdx.x;
    const int lane = tid & (K4 - 1);
    const int s    = tid >> 6;
    const int bid  = blockIdx.x;
    const int ct   = bid & (SEGR - 1);
    const int b    = bid >> 4;

    const int w     = ct ? WS : 0;
    const int niter = w + SEG / ST;       // 22 or 16
    const size_t f0 = ((size_t)b * 8192 + (size_t)ct * SEG - (size_t)w * ST) * K4;
    const float4* src = d2 + f0;
    float4* q = out + f0 + (size_t)(s * 8) * K4 + lane;

    if (tid == 0) {
        #pragma unroll
        for (int k = 0; k < NST; ++k)
            asm volatile("mbarrier.init.shared.b64 [%0], %1;"
                         :: "r"(mb0 + 8u * k), "r"(1) : "memory");
    }
    __syncthreads();

    // Preamble: launch fills for stages 0..2 (buffers initially free)
    if (tid == 0) {
        #pragma unroll
        for (int k = 0; k < NST; ++k) {
            asm volatile("mbarrier.arrive.expect_tx.shared.b64 _, [%0], %1;"
                         :: "r"(mb0 + 8u * k), "r"(STAGE_BYTES) : "memory");
            asm volatile("cp.async.bulk.shared::cta.global.mbarrier::complete_tx::bytes "
                         "[%0], [%1], %2, [%3];"
                         :: "r"(s2u(stg + (size_t)k * IST)),
                            "l"(src + (size_t)k * IST),
                            "r"(STAGE_BYTES), "r"(mb0 + 8u * k) : "memory");
        }
    }

    float4 C = make_float4(0.f, 0.f, 0.f, 0.f);
    int j = 0, ph = 0;                     // stage ring index, phase parity
    for (int i = 0; i < niter; ++i) {
        // Wait stage full (parity (i/3)&1 == ph by construction)
        asm volatile("{\n\t.reg .pred P;\n\t"
                     "W%=:\n\t"
                     "mbarrier.try_wait.parity.shared.b64 P, [%0], %1;\n\t"
                     "@!P bra W%=;\n\t}"
                     :: "r"(mb0 + 8u * j), "r"(ph) : "memory");

        // Read 8 float4 from stage (conflict-free LDS.128) and scan
        const float4* sp = stg + (size_t)j * IST + (size_t)(s * 8) * K4 + lane;
        float4 xx[8];
        float4 z = make_float4(0.f, 0.f, 0.f, 0.f);
        #pragma unroll
        for (int t = 0; t < 8; ++t) {
            float4 x = sp[t * K4];
            z.x = fmaf(LAM, z.x, OM * x.x);
            z.y = fmaf(LAM, z.y, OM * x.y);
            z.z = fmaf(LAM, z.z, OM * x.z);
            z.w = fmaf(LAM, z.w, OM * x.w);
            xx[t] = z;
        }
        agg[i & 1][s][lane] = z;
        __syncthreads();                   // all stage reads + agg writes done

        // Stage buffer j is now free: immediately re-arm and refill with data i+3
        if (tid == 0 && i + NST < niter) {
            asm volatile("mbarrier.arrive.expect_tx.shared.b64 _, [%0], %1;"
                         :: "r"(mb0 + 8u * j), "r"(STAGE_BYTES) : "memory");
            asm volatile("cp.async.bulk.shared::cta.global.mbarrier::complete_tx::bytes "
                         "[%0], [%1], %2, [%3];"
                         :: "r"(s2u(stg + (size_t)j * IST)),
                            "l"(src + (size_t)(i + NST) * IST),
                            "r"(STAGE_BYTES), "r"(mb0 + 8u * j) : "memory");
        }

        const float4 a0 = agg[i & 1][0][lane], a1 = agg[i & 1][1][lane];
        const float4 a2 = agg[i & 1][2][lane], a3 = agg[i & 1][3][lane];

        if (i >= w) {
            float4 e;                      // exact z at this group's entry
            if      (s == 0) e = C;
            else if (s == 1) e = f4fma(L8,  C, a0);
            else if (s == 2) e = f4fma(L16, C, f4fma(L8, a0, a1));
            else             e = f4fma(L24, C, f4fma(L16, a0, f4fma(L8, a1, a2)));
            float4 cf = e;
            #pragma unroll
            for (int t = 0; t < 8; ++t) {
                cf = f4s(LAM, cf);         // e * lam^(t+1)
                xx[t].x += cf.x; xx[t].y += cf.y;
                xx[t].z += cf.z; xx[t].w += cf.w;
                q[(size_t)i * IST + t * K4] = xx[t];
            }
        }
        float4 Af = f4fma(L8, f4fma(L8, f4fma(L8, a0, a1), a2), a3);
        C = f4fma(L32, C, Af);

        if (++j == NST) { j = 0; ph ^= 1; }
    }
}

extern "C" void kernel_launch(void* const* d_in, const int* in_sizes, int n_in,
                              void* d_out, int out_size) {
    (void)in_sizes; (void)n_in; (void)out_size;
    const float4* d2 = (const float4*)d_in[0];
    float4* out = (float4*)d_out;

    cudaFuncSetAttribute(pft_scan, cudaFuncAttributeMaxDynamicSharedMemorySize, SMEM_BYTES);
    pft_scan<<<NCTA, 256, SMEM_BYTES>>>(d2, out);
}